// round 9
// baseline (speedup 1.0000x reference)
#include <cuda_runtime.h>
#include <cstdint>

// Problem constants
#define Bn 32
#define Dn 1024
#define Hn 1024
#define BETA 0.9f

// Output layout (reference return order):
//   [0, B*H)              out   = tanh(a)
//   [B*H, 2*B*H)          u_new = a
//   [2*B*H, +B*D*H)       E_w_new = 0.9*E_w + x[i,d]  (broadcast over h)
//   [..., +B*H)           E_b_new = 0.9*E_b + 1
// a[i,h] = 0.9*u[i,h] + sum_d x[i,d]*w[d,h] + b[h]

#define NB_GEMM 128            // 32 i-rows * 4 h-chunks of 256
#define NB_EW   464            // single co-resident wave: 148*4 - 128
#define NWARPS  (NB_EW * 8)    // 3712 stream warps
#define NHR     (Bn * Dn * 2)  // 65536 half-rows of 512 floats
#define OFF_UNEW (Bn*Hn)
#define OFF_EW   (2*Bn*Hn)
#define OFF_EB   (2*Bn*Hn + Bn*Dn*Hn)

// half-row hr: float4 index hr*128 + k*32 + lane, k=0..3
#define LOADB(arr, hr)                                                  \
    do { const float4* _s = e4 + (size_t)(hr) * 128 + lane;             \
         _Pragma("unroll")                                              \
         for (int _k = 0; _k < 4; ++_k) arr[_k] = __ldcs(_s + _k * 32); \
    } while (0)

#define STOREB(arr, hr, xv)                                             \
    do { float4* _o = o4 + (size_t)(hr) * 128 + lane;                   \
         _Pragma("unroll")                                              \
         for (int _k = 0; _k < 4; ++_k) {                               \
             float4 _v;                                                 \
             _v.x = fmaf(BETA, arr[_k].x, xv);                          \
             _v.y = fmaf(BETA, arr[_k].y, xv);                          \
             _v.z = fmaf(BETA, arr[_k].z, xv);                          \
             _v.w = fmaf(BETA, arr[_k].w, xv);                          \
             __stcs(_o + _k * 32, _v);                                  \
         }                                                              \
    } while (0)

__global__ void __launch_bounds__(256, 4)
diag_rtrl_kernel(const float* __restrict__ x,
                 const float* __restrict__ w,
                 const float* __restrict__ b,
                 const float* __restrict__ u,
                 const float* __restrict__ E_w,
                 const float* __restrict__ E_b,
                 float* __restrict__ out)
{
    __shared__ float xs[Dn];   // GEMM path only (4 KB)

    const int bid = blockIdx.x;
    const int t   = threadIdx.x;

    if (bid < NB_GEMM) {
        // ---- GEMM + tanh + u_new + E_b path ----
        const int i     = bid >> 2;          // batch row
        const int hbase = (bid & 3) * 256;   // h chunk

        const float4* xr = reinterpret_cast<const float4*>(x + i * Dn);
        reinterpret_cast<float4*>(xs)[t] = xr[t];
        __syncthreads();

        const int h = hbase + t;
        const float* wc = w + h;
        float acc = 0.0f;
        #pragma unroll 8
        for (int d = 0; d < Dn; ++d) {
            acc = fmaf(xs[d], __ldg(wc + d * Hn), acc);
        }

        const int ih = i * Hn + h;
        const float a = fmaf(BETA, u[ih], acc + b[h]);
        out[ih]            = tanhf(a);
        out[OFF_UNEW + ih] = a;
        out[OFF_EB   + ih] = fmaf(BETA, E_b[ih], 1.0f);
        return;
    }

    // ---- E_w streaming: persistent warps, half-row ping-pong pipeline ----
    const int lane = t & 31;
    const int W    = (bid - NB_GEMM) * 8 + (t >> 5);   // stream warp id
    const int n    = (NHR - 1 - W) / NWARPS + 1;       // half-rows (17-18)

    const float4* e4 = reinterpret_cast<const float4*>(E_w);
    float4*       o4 = reinterpret_cast<float4*>(out + OFF_EW);

    float4 A[4], Bv[4];
    size_t r  = (size_t)W;
    float  xA = __ldg(x + (r >> 1));
    LOADB(A, r);

    size_t rp = r;          // half-row pending in active buffer
    float  xB;
    bool   pa = true;       // pending buffer is A?

    for (int i = 1; i < n; ++i) {
        const size_t rn = (size_t)W + (size_t)i * NWARPS;
        if (pa) {
            xB = __ldg(x + (rn >> 1));
            LOADB(Bv, rn);          // 4 loads in flight...
            STOREB(A, rp, xA);      // ...while draining previous half-row
        } else {
            xA = __ldg(x + (rn >> 1));
            LOADB(A, rn);
            STOREB(Bv, rp, xB);
        }
        rp = rn;
        pa = !pa;
    }
    if (pa) { STOREB(A, rp, xA); } else { STOREB(Bv, rp, xB); }
}

extern "C" void kernel_launch(void* const* d_in, const int* in_sizes, int n_in,
                              void* d_out, int out_size)
{
    const float* x   = (const float*)d_in[0];   // [32,1024]
    const float* w   = (const float*)d_in[1];   // [1024,1024]
    const float* b   = (const float*)d_in[2];   // [1024]
    const float* u   = (const float*)d_in[3];   // [32,1024]
    const float* E_w = (const float*)d_in[4];   // [1,32,1024,1024]
    const float* E_b = (const float*)d_in[5];   // [1,32,1024]
    float* out = (float*)d_out;

    diag_rtrl_kernel<<<NB_GEMM + NB_EW, 256>>>(x, w, b, u, E_w, E_b, out);
}

// round 10
// speedup vs baseline: 1.2685x; 1.2685x over previous
#include <cuda_runtime.h>
#include <cstdint>

// Problem constants
#define Bn 32
#define Dn 1024
#define Hn 1024
#define BETA 0.9f

// Output layout (reference return order):
//   [0, B*H)              out   = tanh(a)
//   [B*H, 2*B*H)          u_new = a
//   [2*B*H, +B*D*H)       E_w_new = 0.9*E_w + x[i,d]  (broadcast over h)
//   [..., +B*H)           E_b_new = 0.9*E_b + 1
// a[i,h] = 0.9*u[i,h] + sum_d x[i,d]*w[d,h] + b[h]

#define NB_GEMM 128            // 32 i-rows * 4 h-chunks of 256
#define NB_EW   316            // one resident wave at 3 blocks/SM: 148*3 - 128
#define NWARPS  (NB_EW * 8)    // 2528 stream warps
#define NHR     (Bn * Dn * 2)  // 65536 half-rows of 512 floats
#define OFF_UNEW (Bn*Hn)
#define OFF_EW   (2*Bn*Hn)
#define OFF_EB   (2*Bn*Hn + Bn*Dn*Hn)

// half-row hr: float4 index hr*128 + k*32 + lane, k=0..3
#define LOADB(arr, hr)                                                  \
    do { const float4* _s = e4 + (size_t)(hr) * 128 + lane;             \
         _Pragma("unroll")                                              \
         for (int _k = 0; _k < 4; ++_k) arr[_k] = __ldcs(_s + _k * 32); \
    } while (0)

#define STOREB(arr, hr, xv)                                             \
    do { float4* _o = o4 + (size_t)(hr) * 128 + lane;                   \
         _Pragma("unroll")                                              \
         for (int _k = 0; _k < 4; ++_k) {                               \
             float4 _v;                                                 \
             _v.x = fmaf(BETA, arr[_k].x, xv);                          \
             _v.y = fmaf(BETA, arr[_k].y, xv);                          \
             _v.z = fmaf(BETA, arr[_k].z, xv);                          \
             _v.w = fmaf(BETA, arr[_k].w, xv);                          \
             __stcs(_o + _k * 32, _v);                                  \
         }                                                              \
    } while (0)

__global__ void __launch_bounds__(256, 3)
diag_rtrl_kernel(const float* __restrict__ x,
                 const float* __restrict__ w,
                 const float* __restrict__ b,
                 const float* __restrict__ u,
                 const float* __restrict__ E_w,
                 const float* __restrict__ E_b,
                 float* __restrict__ out)
{
    __shared__ float xs[Dn];   // GEMM path only (4 KB)

    const int bid = blockIdx.x;
    const int t   = threadIdx.x;

    if (bid < NB_GEMM) {
        // ---- GEMM + tanh + u_new + E_b path ----
        const int i     = bid >> 2;          // batch row
        const int hbase = (bid & 3) * 256;   // h chunk

        const float4* xr = reinterpret_cast<const float4*>(x + i * Dn);
        reinterpret_cast<float4*>(xs)[t] = xr[t];
        __syncthreads();

        const int h = hbase + t;
        const float* wc = w + h;
        float acc = 0.0f;
        #pragma unroll 8
        for (int d = 0; d < Dn; ++d) {
            acc = fmaf(xs[d], __ldg(wc + d * Hn), acc);
        }

        const int ih = i * Hn + h;
        const float a = fmaf(BETA, u[ih], acc + b[h]);
        out[ih]            = tanhf(a);
        out[OFF_UNEW + ih] = a;
        out[OFF_EB   + ih] = fmaf(BETA, E_b[ih], 1.0f);
        return;
    }

    // ---- E_w streaming: persistent warps, depth-3 half-row ring ----
    // Steady state: half-rows i+1 and i+2 (8 float4/warp) in flight while
    // storing half-row i.
    const int lane = t & 31;
    const int W    = (bid - NB_GEMM) * 8 + (t >> 5);   // stream warp id
    const int n    = (NHR - 1 - W) / NWARPS + 1;       // 25-26 half-rows

    const float4* e4 = reinterpret_cast<const float4*>(E_w);
    float4*       o4 = reinterpret_cast<float4*>(out + OFF_EW);

    float4 A[4], B4[4], C[4];
    float  xA = 0.f, xB = 0.f, xC = 0.f;

    {   // prologue: hr(0) -> A, hr(1) -> B
        const size_t h0 = (size_t)W;
        xA = __ldg(x + (h0 >> 1));
        LOADB(A, h0);
        if (n > 1) {
            const size_t h1 = h0 + NWARPS;
            xB = __ldg(x + (h1 >> 1));
            LOADB(B4, h1);
        }
    }

    for (int i = 0; i < n; ++i) {
        const size_t hs = (size_t)W + (size_t)i * NWARPS;   // store target
        const int ph = i % 3;
        if (i + 2 < n) {
            const size_t hl = hs + 2 * (size_t)NWARPS;      // load target
            if (ph == 0)      { xC = __ldg(x + (hl >> 1)); LOADB(C,  hl); }
            else if (ph == 1) { xA = __ldg(x + (hl >> 1)); LOADB(A,  hl); }
            else              { xB = __ldg(x + (hl >> 1)); LOADB(B4, hl); }
        }
        if (ph == 0)      { STOREB(A,  hs, xA); }
        else if (ph == 1) { STOREB(B4, hs, xB); }
        else              { STOREB(C,  hs, xC); }
    }
}

extern "C" void kernel_launch(void* const* d_in, const int* in_sizes, int n_in,
                              void* d_out, int out_size)
{
    const float* x   = (const float*)d_in[0];   // [32,1024]
    const float* w   = (const float*)d_in[1];   // [1024,1024]
    const float* b   = (const float*)d_in[2];   // [1024]
    const float* u   = (const float*)d_in[3];   // [32,1024]
    const float* E_w = (const float*)d_in[4];   // [1,32,1024,1024]
    const float* E_b = (const float*)d_in[5];   // [1,32,1024]
    float* out = (float*)d_out;

    diag_rtrl_kernel<<<NB_GEMM + NB_EW, 256>>>(x, w, b, u, E_w, E_b, out);
}